// round 12
// baseline (speedup 1.0000x reference)
#include <cuda_runtime.h>
#include <cstdint>

#define NQ 8
#define HD 256
#define S_TOT 8192
#define PAST 8191
#define HID 1536
#define INTER 6144
#define QDIM 2048
#define SCALE 0.0625f
#define NCHUNK 512          // 8192 / 16
#define CHUNK 16

// -------- scratch (device globals) --------
__device__ float g_qkvacc[2560];           // preset biases by k_zero; k_qkv atomically adds W sums
__device__ float g_avpart[NCHUNK * 2048];  // per-chunk partial AV
__device__ float g_stm[NCHUNK * 8];
__device__ float g_stl[NCHUNK * 8];
__device__ float g_attn[QDIM];
__device__ float g_h1[HID];                // preset x+bo by k_comb; k_wo atomics add
__device__ float g_gup[384 * INTER];       // gate partials [0:192), up partials [192:384)
__device__ float g_mid[INTER];

static __device__ __forceinline__ float gelu_exact(float v) {
    return 0.5f * v * (1.0f + erff(v * 0.70710678118654752f));
}
static __device__ __forceinline__ void cp16(uint32_t dst, const void* src) {
    asm volatile("cp.async.cg.shared.global [%0], [%1], 16;" :: "r"(dst), "l"(src));
}
static __device__ __forceinline__ void cp_commit() {
    asm volatile("cp.async.commit_group;");
}
template<int N> static __device__ __forceinline__ void cp_wait() {
    asm volatile("cp.async.wait_group %0;" :: "n"(N));
}
static __device__ __forceinline__ uint32_t smem_u32(const void* p) {
    return (uint32_t)__cvta_generic_to_shared(p);
}

// ============ K0: preset g_qkvacc = [bq, bk, bv] ============
__global__ __launch_bounds__(256) void k_zero(
        const float* __restrict__ bq, const float* __restrict__ bk,
        const float* __restrict__ bv) {
    int t = threadIdx.x;
#pragma unroll
    for (int i = 0; i < 8; i++) g_qkvacc[i * 256 + t] = bq[i * 256 + t];
    g_qkvacc[2048 + t] = bk[t];
    g_qkvacc[2304 + t] = bv[t];
}

// ============ K1: QKV projection via cp.async staging + atomic combine ============
// 160 blocks x 256. b<128: Wq stripe (12 rows, chunks of 3); b<144: Wk stripe (96 rows,
// chunks of 24); else Wv. Chunk = 24KB (1536 float4), double-buffered.
__global__ __launch_bounds__(256) void k_qkv(
        const float* __restrict__ x,
        const float* __restrict__ Wq, const float* __restrict__ Wk,
        const float* __restrict__ Wv) {
    __shared__ float4 buf[2][1536];
    int t = threadIdx.x, b = blockIdx.x;
    const float4* src; int r0, isQ, type;
    if (b < 128)      { src = (const float4*)Wq; r0 = b * 12;         isQ = 1; type = 0; }
    else if (b < 144) { src = (const float4*)Wk; r0 = (b - 128) * 96; isQ = 0; type = 1; }
    else              { src = (const float4*)Wv; r0 = (b - 144) * 96; isQ = 0; type = 2; }
    const float4* sb = src + (size_t)r0 * (isQ ? 512 : 64);
    uint32_t s0 = smem_u32(&buf[0][0]), s1 = smem_u32(&buf[1][0]);
    {   // issue chunks 0,1
#pragma unroll
        for (int i = 0; i < 6; i++) cp16(s0 + (t + i * 256) * 16, sb + t + i * 256);
        cp_commit();
#pragma unroll
        for (int i = 0; i < 6; i++) cp16(s1 + (t + i * 256) * 16, sb + 1536 + t + i * 256);
        cp_commit();
    }
    float acc[8];
#pragma unroll
    for (int j = 0; j < 8; j++) acc[j] = 0.f;
#pragma unroll
    for (int c = 0; c < 4; c++) {
        if (c < 3) cp_wait<1>(); else cp_wait<0>();
        __syncthreads();
        const float* cb = (const float*)buf[c & 1];
        if (isQ) {
#pragma unroll
            for (int r = 0; r < 3; r++) {
                float xv = __ldg(x + r0 + c * 3 + r);
#pragma unroll
                for (int j = 0; j < 8; j++) acc[j] += xv * cb[r * 2048 + j * 256 + t];
            }
        } else {
#pragma unroll
            for (int r = 0; r < 24; r++) {
                float xv = __ldg(x + r0 + c * 24 + r);
                acc[0] += xv * cb[r * 256 + t];
            }
        }
        __syncthreads();
        if (c < 2) {
            uint32_t d = (c & 1) ? s1 : s0;   // FIX: refill the buffer just consumed
            const float4* s = sb + (c + 2) * 1536;
#pragma unroll
            for (int i = 0; i < 6; i++) cp16(d + (t + i * 256) * 16, s + t + i * 256);
            cp_commit();
        }
    }
    if (isQ) {
#pragma unroll
        for (int j = 0; j < 8; j++) atomicAdd(&g_qkvacc[j * 256 + t], acc[j]);
    } else if (type == 1) {
        atomicAdd(&g_qkvacc[2048 + t], acc[0]);
    } else {
        atomicAdd(&g_qkvacc[2304 + t], acc[0]);
    }
}

// ============ K2: flash-decode partial with staged K/V tiles ============
// 512 blocks x 256. Chunk of 16 KV rows; K tile 16KB + V tile 16KB via cp.async.
__global__ __launch_bounds__(256) void k_attn(
        const float* __restrict__ kp, const float* __restrict__ vp) {
    __shared__ float Ks[16 * 256];
    __shared__ float Vs[16 * 256];
    __shared__ float s_sm[8][CHUNK];
    int t = threadIdx.x, lane = t & 31, wid = t >> 5;
    int c = blockIdx.x;
    int sBase = c * CHUNK;
    uint32_t ks = smem_u32(Ks), vs = smem_u32(Vs);
    const float4* kp4 = (const float4*)kp + (size_t)sBase * 64;
    const float4* vp4 = (const float4*)vp + (size_t)sBase * 64;
    bool last = (c == NCHUNK - 1);
    {   // issue K group then V group (skip row 8191 — patched from g_qkvacc)
#pragma unroll
        for (int i = 0; i < 4; i++) {
            int idx = t + i * 256;
            if (!last || (idx >> 6) < 15) cp16(ks + idx * 16, kp4 + idx);
        }
        cp_commit();
#pragma unroll
        for (int i = 0; i < 4; i++) {
            int idx = t + i * 256;
            if (!last || (idx >> 6) < 15) cp16(vs + idx * 16, vp4 + idx);
        }
        cp_commit();
    }
    // q for all 8 heads (bias already in g_qkvacc; apply SCALE here)
    float4 qa[8], qb[8];
#pragma unroll
    for (int h = 0; h < 8; h++) {
        float4 a = *(const float4*)&g_qkvacc[h * 256 + lane * 8];
        float4 bb = *(const float4*)&g_qkvacc[h * 256 + lane * 8 + 4];
        qa[h] = make_float4(a.x * SCALE, a.y * SCALE, a.z * SCALE, a.w * SCALE);
        qb[h] = make_float4(bb.x * SCALE, bb.y * SCALE, bb.z * SCALE, bb.w * SCALE);
    }
    cp_wait<1>();
    if (last) Ks[15 * 256 + t] = g_qkvacc[2048 + t];
    __syncthreads();
    // ---- Phase 1: scores; warp wid handles rows wid*2, wid*2+1
    {
        int r0 = wid * 2, r1 = r0 + 1;
        float4 ka0 = *(const float4*)&Ks[r0 * 256 + lane * 8];
        float4 kb0 = *(const float4*)&Ks[r0 * 256 + lane * 8 + 4];
        float4 ka1 = *(const float4*)&Ks[r1 * 256 + lane * 8];
        float4 kb1 = *(const float4*)&Ks[r1 * 256 + lane * 8 + 4];
        float a0[8], a1[8];
#pragma unroll
        for (int h = 0; h < 8; h++) {
            a0[h] = qa[h].x * ka0.x + qa[h].y * ka0.y + qa[h].z * ka0.z + qa[h].w * ka0.w
                  + qb[h].x * kb0.x + qb[h].y * kb0.y + qb[h].z * kb0.z + qb[h].w * kb0.w;
            a1[h] = qa[h].x * ka1.x + qa[h].y * ka1.y + qa[h].z * ka1.z + qa[h].w * ka1.w
                  + qb[h].x * kb1.x + qb[h].y * kb1.y + qb[h].z * kb1.z + qb[h].w * kb1.w;
        }
#pragma unroll
        for (int h = 0; h < 8; h++) {
#pragma unroll
            for (int off = 16; off; off >>= 1) {
                a0[h] += __shfl_xor_sync(0xffffffffu, a0[h], off);
                a1[h] += __shfl_xor_sync(0xffffffffu, a1[h], off);
            }
        }
        if (lane < 8) {
            s_sm[lane][r0] = a0[lane];
            s_sm[lane][r1] = a1[lane];
        }
    }
    __syncthreads();
    // ---- Phase 2: per-head local softmax (16 cols; dup-lane trick, sum halved)
    {
        float s = s_sm[wid][lane & 15];
        float m = s;
#pragma unroll
        for (int off = 16; off; off >>= 1) m = fmaxf(m, __shfl_xor_sync(0xffffffffu, m, off));
        float p = __expf(s - m);
        float l = p;
#pragma unroll
        for (int off = 16; off; off >>= 1) l += __shfl_xor_sync(0xffffffffu, l, off);
        l *= 0.5f;
        if (lane < 16) s_sm[wid][lane] = p;
        if (lane == 0) { g_stm[c * 8 + wid] = m; g_stl[c * 8 + wid] = l; }
    }
    cp_wait<0>();
    if (last) Vs[15 * 256 + t] = g_qkvacc[2304 + t];
    __syncthreads();
    // ---- Phase 3: thread owns (head h = t>>5, d8 = (t&31)*8)
    {
        int h = t >> 5, d8 = (t & 31) * 8;
        float4 acc0 = make_float4(0.f, 0.f, 0.f, 0.f);
        float4 acc1 = make_float4(0.f, 0.f, 0.f, 0.f);
#pragma unroll
        for (int pos = 0; pos < 16; pos++) {
            float pw = s_sm[h][pos];
            float4 v0 = *(const float4*)&Vs[pos * 256 + d8];
            float4 v1 = *(const float4*)&Vs[pos * 256 + d8 + 4];
            acc0.x += pw * v0.x; acc0.y += pw * v0.y; acc0.z += pw * v0.z; acc0.w += pw * v0.w;
            acc1.x += pw * v1.x; acc1.y += pw * v1.y; acc1.z += pw * v1.z; acc1.w += pw * v1.w;
        }
        float* outp = g_avpart + (size_t)c * 2048 + h * 256 + d8;
        *(float4*)outp = acc0;
        *(float4*)(outp + 4) = acc1;
    }
}

// ============ K3: combine partials -> g_attn; preset g_h1 = x + bo ============
// 32 blocks x 256 (NCHUNK=512).
__global__ __launch_bounds__(256) void k_comb(
        const float* __restrict__ x, const float* __restrict__ bo) {
    __shared__ float w_sm[NCHUNK * 8];
    __shared__ float4 red2[256];
    int t = threadIdx.x, lane = t & 31, wid = t >> 5;
    float mv[16], lv[16];
#pragma unroll
    for (int i = 0; i < 16; i++) {
        int c = lane * 16 + i;
        mv[i] = g_stm[c * 8 + wid];
        lv[i] = g_stl[c * 8 + wid];
    }
    float M = mv[0];
#pragma unroll
    for (int i = 1; i < 16; i++) M = fmaxf(M, mv[i]);
#pragma unroll
    for (int off = 16; off; off >>= 1) M = fmaxf(M, __shfl_xor_sync(0xffffffffu, M, off));
    float L = 0.f;
#pragma unroll
    for (int i = 0; i < 16; i++) L += __expf(mv[i] - M) * lv[i];
#pragma unroll
    for (int off = 16; off; off >>= 1) L += __shfl_xor_sync(0xffffffffu, L, off);
    float invL = 1.0f / L;
#pragma unroll
    for (int i = 0; i < 16; i++) {
        int c = lane * 16 + i;
        w_sm[c * 8 + wid] = __expf(mv[i] - M) * invL;
    }
    if (blockIdx.x < 6) {
        int idx = blockIdx.x * 256 + t;
        g_h1[idx] = x[idx] + bo[idx];
    }
    __syncthreads();
    int oLoc = t & 15, sl = t >> 4;
    int o = blockIdx.x * 16 + oLoc;
    int h = o >> 6;
    float4 acc = make_float4(0.f, 0.f, 0.f, 0.f);
#pragma unroll
    for (int b = 0; b < 4; b++) {
        float4 vv[8];
#pragma unroll
        for (int i = 0; i < 8; i++) {
            int cidx = sl + (b * 8 + i) * 16;
            vv[i] = *(const float4*)(g_avpart + (size_t)cidx * 2048 + o * 4);
        }
#pragma unroll
        for (int i = 0; i < 8; i++) {
            int cidx = sl + (b * 8 + i) * 16;
            float w = w_sm[cidx * 8 + h];
            acc.x += w * vv[i].x; acc.y += w * vv[i].y; acc.z += w * vv[i].z; acc.w += w * vv[i].w;
        }
    }
    red2[t] = acc;
    __syncthreads();
    if (t < 16) {
        float4 s = red2[t];
#pragma unroll
        for (int j = 1; j < 16; j++) {
            float4 b2 = red2[t + 16 * j];
            s.x += b2.x; s.y += b2.y; s.z += b2.z; s.w += b2.w;
        }
        ((float4*)g_attn)[blockIdx.x * 16 + t] = s;
    }
}

// ============ K4: g_h1 += attn @ Wo (staged stripes of 8 rows) ============
// 256 blocks x 256. Chunk = 4 rows (1536 f4 = 24KB), 2 chunks, double-buffered.
__global__ __launch_bounds__(256) void k_wo(const float* __restrict__ Wo) {
    __shared__ float4 buf[2][1536];
    int t = threadIdx.x;
    int r0 = blockIdx.x * 8;
    const float4* sb = (const float4*)Wo + (size_t)r0 * 384;
    uint32_t s0 = smem_u32(&buf[0][0]), s1 = smem_u32(&buf[1][0]);
#pragma unroll
    for (int i = 0; i < 6; i++) cp16(s0 + (t + i * 256) * 16, sb + t + i * 256);
    cp_commit();
#pragma unroll
    for (int i = 0; i < 6; i++) cp16(s1 + (t + i * 256) * 16, sb + 1536 + t + i * 256);
    cp_commit();
    float acc[6];
#pragma unroll
    for (int j = 0; j < 6; j++) acc[j] = 0.f;
#pragma unroll
    for (int c = 0; c < 2; c++) {
        if (c == 0) cp_wait<1>(); else cp_wait<0>();
        __syncthreads();
        const float* cb = (const float*)buf[c];
#pragma unroll
        for (int r = 0; r < 4; r++) {
            float xv = g_attn[r0 + c * 4 + r];
#pragma unroll
            for (int j = 0; j < 6; j++) acc[j] += xv * cb[r * 1536 + j * 256 + t];
        }
        __syncthreads();
    }
#pragma unroll
    for (int j = 0; j < 6; j++) atomicAdd(&g_h1[j * 256 + t], acc[j]);
}

// ============ K5: gate/up partials (staged stripes of 8 rows, chunk = 1 row) ============
// 384 blocks x 256. b<192: Wg stripe b; else Wu stripe b-192. Partials to g_gup.
__global__ __launch_bounds__(256) void k_gu(
        const float* __restrict__ Wg, const float* __restrict__ Wu) {
    __shared__ float4 buf[2][1536];
    int t = threadIdx.x, b = blockIdx.x;
    int mat = (b >= 192);
    int stripe = mat ? (b - 192) : b;
    int r0 = stripe * 8;
    const float4* sb = (const float4*)(mat ? Wu : Wg) + (size_t)r0 * 1536;
    uint32_t s0 = smem_u32(&buf[0][0]), s1 = smem_u32(&buf[1][0]);
#pragma unroll
    for (int i = 0; i < 6; i++) cp16(s0 + (t + i * 256) * 16, sb + t + i * 256);
    cp_commit();
#pragma unroll
    for (int i = 0; i < 6; i++) cp16(s1 + (t + i * 256) * 16, sb + 1536 + t + i * 256);
    cp_commit();
    float acc[24];
#pragma unroll
    for (int j = 0; j < 24; j++) acc[j] = 0.f;
#pragma unroll
    for (int c = 0; c < 8; c++) {
        if (c < 7) cp_wait<1>(); else cp_wait<0>();
        __syncthreads();
        const float* cb = (const float*)buf[c & 1];
        float xv = g_h1[r0 + c];
#pragma unroll
        for (int j = 0; j < 24; j++) acc[j] += xv * cb[j * 256 + t];
        __syncthreads();
        if (c < 6) {
            uint32_t d = (c & 1) ? s1 : s0;   // FIX: refill the buffer just consumed
            const float4* s = sb + (size_t)(c + 2) * 1536;
#pragma unroll
            for (int i = 0; i < 6; i++) cp16(d + (t + i * 256) * 16, s + t + i * 256);
            cp_commit();
        }
    }
    float* dst = g_gup + (size_t)b * INTER;
#pragma unroll
    for (int j = 0; j < 24; j++) dst[j * 256 + t] = acc[j];
}

// ============ K6: mid = gelu(sum gate + bg)*(sum up + bu); preset out = h1 + bd ====
// 15 blocks x 512.
__global__ __launch_bounds__(512) void k_mid(
        const float* __restrict__ bg, const float* __restrict__ bu,
        const float* __restrict__ bd, float* __restrict__ out) {
    int t = threadIdx.x;
    if (blockIdx.x < 12) {
        int col = blockIdx.x * 512 + t;
        float g0 = 0.f, g1 = 0.f, u0 = 0.f, u1 = 0.f;
#pragma unroll 8
        for (int s = 0; s < 192; s += 2) {
            g0 += g_gup[(size_t)s * INTER + col];
            g1 += g_gup[(size_t)(s + 1) * INTER + col];
            u0 += g_gup[(size_t)(192 + s) * INTER + col];
            u1 += g_gup[(size_t)(193 + s) * INTER + col];
        }
        float ga = g0 + g1 + bg[col];
        float ua = u0 + u1 + bu[col];
        g_mid[col] = gelu_exact(ga) * ua;
    } else {
        int idx = (blockIdx.x - 12) * 512 + t;
        out[idx] = g_h1[idx] + bd[idx];
    }
}

// ============ K7: out += mid @ Wd (staged stripes of 16 rows, chunk = 4 rows) ============
// 384 blocks x 256.
__global__ __launch_bounds__(256) void k_down(
        const float* __restrict__ Wd, float* __restrict__ out) {
    __shared__ float4 buf[2][1536];
    int t = threadIdx.x;
    int r0 = blockIdx.x * 16;
    const float4* sb = (const float4*)Wd + (size_t)r0 * 384;
    uint32_t s0 = smem_u32(&buf[0][0]), s1 = smem_u32(&buf[1][0]);
#pragma unroll
    for (int i = 0; i < 6; i++) cp16(s0 + (t + i * 256) * 16, sb + t + i * 256);
    cp_commit();
#pragma unroll
    for (int i = 0; i < 6; i++) cp16(s1 + (t + i * 256) * 16, sb + 1536 + t + i * 256);
    cp_commit();
    float acc[6];
#pragma unroll
    for (int j = 0; j < 6; j++) acc[j] = 0.f;
#pragma unroll
    for (int c = 0; c < 4; c++) {
        if (c < 3) cp_wait<1>(); else cp_wait<0>();
        __syncthreads();
        const float* cb = (const float*)buf[c & 1];
#pragma unroll
        for (int r = 0; r < 4; r++) {
            float xv = g_mid[r0 + c * 4 + r];
#pragma unroll
            for (int j = 0; j < 6; j++) acc[j] += xv * cb[r * 1536 + j * 256 + t];
        }
        __syncthreads();
        if (c < 2) {
            uint32_t d = (c & 1) ? s1 : s0;   // FIX: refill the buffer just consumed
            const float4* s = sb + (size_t)(c + 2) * 1536;
#pragma unroll
            for (int i = 0; i < 6; i++) cp16(d + (t + i * 256) * 16, s + t + i * 256);
            cp_commit();
        }
    }
#pragma unroll
    for (int j = 0; j < 6; j++) atomicAdd(&out[j * 256 + t], acc[j]);
}

extern "C" void kernel_launch(void* const* d_in, const int* in_sizes, int n_in,
                              void* d_out, int out_size) {
    const float* x  = (const float*)d_in[0];
    const float* kp = (const float*)d_in[1];
    const float* vp = (const float*)d_in[2];
    const float* Wq = (const float*)d_in[3];
    const float* bq = (const float*)d_in[4];
    const float* Wk = (const float*)d_in[5];
    const float* bk = (const float*)d_in[6];
    const float* Wv = (const float*)d_in[7];
    const float* bv = (const float*)d_in[8];
    const float* Wo = (const float*)d_in[9];
    const float* bo = (const float*)d_in[10];
    const float* Wg = (const float*)d_in[11];
    const float* bg = (const float*)d_in[12];
    const float* Wu = (const float*)d_in[13];
    const float* bu = (const float*)d_in[14];
    const float* Wd = (const float*)d_in[15];
    const float* bd = (const float*)d_in[16];

    k_zero<<<1,   256>>>(bq, bk, bv);
    k_qkv <<<160, 256>>>(x, Wq, Wk, Wv);
    k_attn<<<512, 256>>>(kp, vp);
    k_comb<<<32,  256>>>(x, bo);
    k_wo  <<<256, 256>>>(Wo);
    k_gu  <<<384, 256>>>(Wg, Wu);
    k_mid <<<15,  512>>>(bg, bu, bd, (float*)d_out);
    k_down<<<384, 256>>>(Wd, (float*)d_out);
}

// round 14
// speedup vs baseline: 1.3009x; 1.3009x over previous
#include <cuda_runtime.h>
#include <cstdint>

#define NQ 8
#define HD 256
#define S_TOT 8192
#define PAST 8191
#define HID 1536
#define INTER 6144
#define QDIM 2048
#define SCALE 0.0625f
#define NCHUNK 256          // 8192 / 32
#define CHUNK 32

// -------- scratch (device globals) --------
__device__ float g_qkv[2560];              // q[0:2048] (pre-scaled), k_new[2048:2304], v_new[2304:2560]
__device__ float g_avpart[NCHUNK * 2048];  // per-chunk partial AV
__device__ float g_stm[NCHUNK * 8];
__device__ float g_stl[NCHUNK * 8];
__device__ float g_attn[QDIM];
__device__ float g_h1[HID];                // preset x+bo by k_comb; k_wo atomics add
__device__ float g_gate[INTER];            // preset bg by k_qkv tail blocks; k_gu atomics add
__device__ float g_up[INTER];              // preset bu by k_qkv tail blocks; k_gu atomics add
__device__ float g_mid[INTER];

static __device__ __forceinline__ float4 f4add(float4 a, float4 b) {
    a.x += b.x; a.y += b.y; a.z += b.z; a.w += b.w; return a;
}
static __device__ __forceinline__ void f4fma(float4& a, float s, float4 w) {
    a.x += s * w.x; a.y += s * w.y; a.z += s * w.z; a.w += s * w.w;
}
static __device__ __forceinline__ float gelu_exact(float v) {
    return 0.5f * v * (1.0f + erff(v * 0.70710678118654752f));
}
template<int PMIN>
static __device__ __forceinline__ float4 wred(float4 v) {
#pragma unroll
    for (int off = 16; off >= PMIN; off >>= 1) {
        v.x += __shfl_xor_sync(0xffffffffu, v.x, off);
        v.y += __shfl_xor_sync(0xffffffffu, v.y, off);
        v.z += __shfl_xor_sync(0xffffffffu, v.z, off);
        v.w += __shfl_xor_sync(0xffffffffu, v.w, off);
    }
    return v;
}
static __device__ __forceinline__ uint32_t smem_u32(const void* p) {
    return (uint32_t)__cvta_generic_to_shared(p);
}
// ---- bulk-DMA (TMA-engine) helpers ----
static __device__ __forceinline__ void mb_init(void* m) {
    asm volatile("mbarrier.init.shared.b64 [%0], 1;" :: "r"(smem_u32(m)));
}
static __device__ __forceinline__ void mb_expect(void* m, int bytes) {
    asm volatile("mbarrier.arrive.expect_tx.shared.b64 _, [%0], %1;"
                 :: "r"(smem_u32(m)), "r"(bytes));
}
static __device__ __forceinline__ void bulk_g2s(void* dst, const void* src, int bytes, void* m) {
    asm volatile("cp.async.bulk.shared::cluster.global.mbarrier::complete_tx::bytes "
                 "[%0], [%1], %2, [%3];"
                 :: "r"(smem_u32(dst)), "l"(src), "r"(bytes), "r"(smem_u32(m)) : "memory");
}
static __device__ __forceinline__ void mb_wait(void* m, int parity) {
    asm volatile("{\n\t.reg .pred P;\nWL_%=:\n\t"
                 "mbarrier.try_wait.parity.shared.b64 P, [%0], %1;\n\t"
                 "@!P bra WL_%=;\n\t}"
                 :: "r"(smem_u32(m)), "r"(parity) : "memory");
}

// ============ K1: QKV projection (+bias, q pre-scaled); tail blocks preset g_gate/g_up ====
// 344 blocks x 512 thr. Blocks 0..319 = R6 QKV; blocks 320..343 preset gate/up biases.
__global__ __launch_bounds__(512) void k_qkv(
        const float* __restrict__ x,
        const float* __restrict__ Wq, const float* __restrict__ bq,
        const float* __restrict__ Wk, const float* __restrict__ bk,
        const float* __restrict__ Wv, const float* __restrict__ bv,
        const float* __restrict__ bg, const float* __restrict__ bu) {
    __shared__ float4 part[16 * 2];
    int t = threadIdx.x, lane = t & 31, wid = t >> 5;
    if (blockIdx.x >= 320) {
        int b = blockIdx.x - 320;          // 0..23
        if (b < 12) g_gate[b * 512 + t] = bg[b * 512 + t];
        else        g_up[(b - 12) * 512 + t] = bu[(b - 12) * 512 + t];
        return;
    }
    int c4 = t & 1, rg = t >> 1;
    int colBase = blockIdx.x * 8;
    const float* W; const float* bias; int ld, wcol; float sc;
    if (blockIdx.x < 256)      { W = Wq; bias = bq; ld = 2048; wcol = colBase;        sc = SCALE; }
    else if (blockIdx.x < 288) { W = Wk; bias = bk; ld = 256;  wcol = colBase - 2048; sc = 1.0f; }
    else                       { W = Wv; bias = bv; ld = 256;  wcol = colBase - 2304; sc = 1.0f; }
    const float* wp = W + wcol + c4 * 4;
    float4 acc = make_float4(0.f, 0.f, 0.f, 0.f);
    int r0 = rg * 6;
#pragma unroll
    for (int i = 0; i < 6; i++) {
        int r = r0 + i;
        float xv = __ldg(x + r);
        float4 w = *(const float4*)(wp + (size_t)r * ld);
        f4fma(acc, xv, w);
    }
    acc = wred<2>(acc);
    if (lane < 2) part[wid * 2 + lane] = acc;
    __syncthreads();
    if (t < 2) {
        float4 s = part[t];
#pragma unroll
        for (int w = 1; w < 16; w++) s = f4add(s, part[w * 2 + t]);
        int col = wcol + t * 4;
        float4 b = *(const float4*)(bias + col);
        s = f4add(s, b);
        s.x *= sc; s.y *= sc; s.z *= sc; s.w *= sc;
        *(float4*)&g_qkv[colBase + t * 4] = s;
    }
}

// ============ K2: fused flash-decode partial ============ (R6 verbatim)
__global__ __launch_bounds__(256, 2) void k_attn(
        const float* __restrict__ kp, const float* __restrict__ vp) {
    __shared__ float s_sm[8][CHUNK];
    __shared__ float4 red[4 * 8 * 64];
    int t = threadIdx.x, lane = t & 31, wid = t >> 5;
    int c = blockIdx.x;
    int sBase = c * CHUNK;
    float4 qa[8], qb[8];
#pragma unroll
    for (int h = 0; h < 8; h++) {
        qa[h] = *(const float4*)(g_qkv + h * 256 + lane * 8);
        qb[h] = *(const float4*)(g_qkv + h * 256 + lane * 8 + 4);
    }
#pragma unroll
    for (int it = 0; it < 2; it++) {
        int r0 = sBase + wid * 4 + it * 2;
        int r1 = r0 + 1;
        const float* kr0 = (r0 < PAST) ? (kp + (size_t)r0 * 256) : (g_qkv + 2048);
        const float* kr1 = (r1 < PAST) ? (kp + (size_t)r1 * 256) : (g_qkv + 2048);
        float4 ka0 = *(const float4*)(kr0 + lane * 8);
        float4 kb0 = *(const float4*)(kr0 + lane * 8 + 4);
        float4 ka1 = *(const float4*)(kr1 + lane * 8);
        float4 kb1 = *(const float4*)(kr1 + lane * 8 + 4);
        float a0[8], a1[8];
#pragma unroll
        for (int h = 0; h < 8; h++) {
            a0[h] = qa[h].x * ka0.x + qa[h].y * ka0.y + qa[h].z * ka0.z + qa[h].w * ka0.w
                  + qb[h].x * kb0.x + qb[h].y * kb0.y + qb[h].z * kb0.z + qb[h].w * kb0.w;
            a1[h] = qa[h].x * ka1.x + qa[h].y * ka1.y + qa[h].z * ka1.z + qa[h].w * ka1.w
                  + qb[h].x * kb1.x + qb[h].y * kb1.y + qb[h].z * kb1.z + qb[h].w * kb1.w;
        }
#pragma unroll
        for (int h = 0; h < 8; h++) {
#pragma unroll
            for (int off = 16; off; off >>= 1) {
                a0[h] += __shfl_xor_sync(0xffffffffu, a0[h], off);
                a1[h] += __shfl_xor_sync(0xffffffffu, a1[h], off);
            }
        }
        if (lane < 8) {
            s_sm[lane][wid * 4 + it * 2]     = a0[lane];
            s_sm[lane][wid * 4 + it * 2 + 1] = a1[lane];
        }
    }
    __syncthreads();
    {
        float s = s_sm[wid][lane];
        float m = s;
#pragma unroll
        for (int off = 16; off; off >>= 1) m = fmaxf(m, __shfl_xor_sync(0xffffffffu, m, off));
        float p = __expf(s - m);
        float l = p;
#pragma unroll
        for (int off = 16; off; off >>= 1) l += __shfl_xor_sync(0xffffffffu, l, off);
        s_sm[wid][lane] = p;
        if (lane == 0) { g_stm[c * 8 + wid] = m; g_stl[c * 8 + wid] = l; }
    }
    __syncthreads();
    int d4 = t & 63, g = t >> 6;
    float4 acc[8];
#pragma unroll
    for (int h = 0; h < 8; h++) acc[h] = make_float4(0.f, 0.f, 0.f, 0.f);
    float4 v[8];
#pragma unroll
    for (int j = 0; j < 8; j++) {
        int s = sBase + g * 8 + j;
        const float* vrow = (s < PAST) ? (vp + (size_t)s * 256) : (g_qkv + 2304);
        v[j] = *(const float4*)(vrow + d4 * 4);
    }
#pragma unroll
    for (int j = 0; j < 8; j++) {
        int pos = g * 8 + j;
#pragma unroll
        for (int h = 0; h < 8; h++) f4fma(acc[h], s_sm[h][pos], v[j]);
    }
#pragma unroll
    for (int h = 0; h < 8; h++) red[g * 512 + h * 64 + d4] = acc[h];
    __syncthreads();
    float4* outp = (float4*)(g_avpart + (size_t)c * 2048);
#pragma unroll
    for (int k = 0; k < 2; k++) {
        int o = t + k * 256;
        float4 s = f4add(f4add(red[o], red[512 + o]), f4add(red[1024 + o], red[1536 + o]));
        outp[o] = s;
    }
}

// ============ K3: combine -> g_attn; preset g_h1 = x + bo ============ (R9 verbatim)
__global__ __launch_bounds__(256) void k_comb(
        const float* __restrict__ x, const float* __restrict__ bo) {
    __shared__ float w_sm[NCHUNK * 8];
    __shared__ float4 red2[256];
    int t = threadIdx.x, lane = t & 31, wid = t >> 5;
    float mv[8], lv[8];
#pragma unroll
    for (int i = 0; i < 8; i++) {
        int c = lane * 8 + i;
        mv[i] = g_stm[c * 8 + wid];
        lv[i] = g_stl[c * 8 + wid];
    }
    float M = mv[0];
#pragma unroll
    for (int i = 1; i < 8; i++) M = fmaxf(M, mv[i]);
#pragma unroll
    for (int off = 16; off; off >>= 1) M = fmaxf(M, __shfl_xor_sync(0xffffffffu, M, off));
    float L = 0.f;
#pragma unroll
    for (int i = 0; i < 8; i++) L += __expf(mv[i] - M) * lv[i];
#pragma unroll
    for (int off = 16; off; off >>= 1) L += __shfl_xor_sync(0xffffffffu, L, off);
    float invL = 1.0f / L;
#pragma unroll
    for (int i = 0; i < 8; i++) {
        int c = lane * 8 + i;
        w_sm[c * 8 + wid] = __expf(mv[i] - M) * invL;
    }
    if (blockIdx.x < 6) {
        int idx = blockIdx.x * 256 + t;
        g_h1[idx] = x[idx] + bo[idx];
    }
    __syncthreads();
    int oLoc = t >> 3, sl = t & 7;
    int o = blockIdx.x * 32 + oLoc;
    int h = o >> 6;
    float4 acc = make_float4(0.f, 0.f, 0.f, 0.f);
#pragma unroll
    for (int b = 0; b < 4; b++) {
        float4 vv[8];
#pragma unroll
        for (int i = 0; i < 8; i++) {
            int c = sl * 32 + b * 8 + i;
            vv[i] = *(const float4*)(g_avpart + (size_t)c * 2048 + o * 4);
        }
#pragma unroll
        for (int i = 0; i < 8; i++) {
            int c = sl * 32 + b * 8 + i;
            f4fma(acc, w_sm[c * 8 + h], vv[i]);
        }
    }
    red2[t] = acc;
    __syncthreads();
    if (t < 32) {
        float4 s = red2[t * 8];
#pragma unroll
        for (int i = 1; i < 8; i++) s = f4add(s, red2[t * 8 + i]);
        ((float4*)g_attn)[blockIdx.x * 32 + t] = s;
    }
}

// ============ K4: g_h1 += attn @ Wo  (bulk-DMA ring-3, stripe = 8 rows) ============
// 256 blocks x 256. 4 chunks x 12KB (2 rows each).
__global__ __launch_bounds__(256) void k_wo(const float* __restrict__ Wo) {
    __shared__ __align__(128) float buf[3][3072];
    __shared__ __align__(8) unsigned long long mbar[3];
    int t = threadIdx.x;
    int r0 = blockIdx.x * 8;
    const char* src = (const char*)(Wo + (size_t)r0 * 1536);
    if (t < 3) mb_init(&mbar[t]);
    __syncthreads();
    if (t == 0) {
#pragma unroll
        for (int b = 0; b < 3; b++) {
            mb_expect(&mbar[b], 12288);
            bulk_g2s(buf[b], src + b * 12288, 12288, &mbar[b]);
        }
    }
    float acc[6];
#pragma unroll
    for (int j = 0; j < 6; j++) acc[j] = 0.f;
#pragma unroll
    for (int c = 0; c < 4; c++) {
        mb_wait(&mbar[c % 3], (c / 3) & 1);
        const float* cb = buf[c % 3];
        float x0 = g_attn[r0 + c * 2], x1 = g_attn[r0 + c * 2 + 1];
#pragma unroll
        for (int j = 0; j < 6; j++)
            acc[j] += x0 * cb[j * 256 + t] + x1 * cb[1536 + j * 256 + t];
        __syncthreads();
        if (c + 3 < 4 && t == 0) {
            mb_expect(&mbar[c % 3], 12288);
            bulk_g2s(buf[c % 3], src + (c + 3) * 12288, 12288, &mbar[c % 3]);
        }
    }
#pragma unroll
    for (int j = 0; j < 6; j++) atomicAdd(&g_h1[j * 256 + t], acc[j]);
}

// ============ K5: gate/up accumulation (bulk-DMA ring-3, stripe = 8 rows) ============
// 384 blocks x 256. b<192: Wg stripe b; else Wu. 16 chunks x 12KB (half-row each).
__global__ __launch_bounds__(256) void k_gu(
        const float* __restrict__ Wg, const float* __restrict__ Wu) {
    __shared__ __align__(128) float buf[3][3072];
    __shared__ __align__(8) unsigned long long mbar[3];
    int t = threadIdx.x, b = blockIdx.x;
    int mat = (b >= 192);
    int stripe = mat ? (b - 192) : b;
    int r0 = stripe * 8;
    const char* src = (const char*)((mat ? Wu : Wg) + (size_t)r0 * 6144);
    if (t < 3) mb_init(&mbar[t]);
    __syncthreads();
    if (t == 0) {
#pragma unroll
        for (int bb = 0; bb < 3; bb++) {
            mb_expect(&mbar[bb], 12288);
            bulk_g2s(buf[bb], src + bb * 12288, 12288, &mbar[bb]);
        }
    }
    float acc[24];
#pragma unroll
    for (int j = 0; j < 24; j++) acc[j] = 0.f;
#pragma unroll
    for (int c = 0; c < 16; c++) {
        mb_wait(&mbar[c % 3], (c / 3) & 1);
        const float* cb = buf[c % 3];
        float xv = g_h1[r0 + (c >> 1)];
        int aBase = (c & 1) * 12;
#pragma unroll
        for (int j = 0; j < 12; j++) acc[aBase + j] += xv * cb[j * 256 + t];
        __syncthreads();
        if (c + 3 < 16 && t == 0) {
            mb_expect(&mbar[c % 3], 12288);
            bulk_g2s(buf[c % 3], src + (size_t)(c + 3) * 12288, 12288, &mbar[c % 3]);
        }
    }
    float* dst = mat ? g_up : g_gate;
#pragma unroll
    for (int j = 0; j < 24; j++) atomicAdd(&dst[j * 256 + t], acc[j]);
}

// ============ K6: mid = gelu(gate)*up; preset out = h1 + bd ============
// 15 blocks x 512.
__global__ __launch_bounds__(512) void k_mid(
        const float* __restrict__ bd, float* __restrict__ out) {
    int t = threadIdx.x;
    if (blockIdx.x < 12) {
        int col = blockIdx.x * 512 + t;
        g_mid[col] = gelu_exact(g_gate[col]) * g_up[col];
    } else {
        int idx = (blockIdx.x - 12) * 512 + t;
        out[idx] = g_h1[idx] + bd[idx];
    }
}

// ============ K7: out += mid @ Wd  (bulk-DMA ring-3, stripe = 16 rows) ============
// 384 blocks x 256. 8 chunks x 12KB (2 rows each).
__global__ __launch_bounds__(256) void k_down(
        const float* __restrict__ Wd, float* __restrict__ out) {
    __shared__ __align__(128) float buf[3][3072];
    __shared__ __align__(8) unsigned long long mbar[3];
    int t = threadIdx.x;
    int r0 = blockIdx.x * 16;
    const char* src = (const char*)(Wd + (size_t)r0 * 1536);
    if (t < 3) mb_init(&mbar[t]);
    __syncthreads();
    if (t == 0) {
#pragma unroll
        for (int b = 0; b < 3; b++) {
            mb_expect(&mbar[b], 12288);
            bulk_g2s(buf[b], src + b * 12288, 12288, &mbar[b]);
        }
    }
    float acc[6];
#pragma unroll
    for (int j = 0; j < 6; j++) acc[j] = 0.f;
#pragma unroll
    for (int c = 0; c < 8; c++) {
        mb_wait(&mbar[c % 3], (c / 3) & 1);
        const float* cb = buf[c % 3];
        float x0 = g_mid[r0 + c * 2], x1 = g_mid[r0 + c * 2 + 1];
#pragma unroll
        for (int j = 0; j < 6; j++)
            acc[j] += x0 * cb[j * 256 + t] + x1 * cb[1536 + j * 256 + t];
        __syncthreads();
        if (c + 3 < 8 && t == 0) {
            mb_expect(&mbar[c % 3], 12288);
            bulk_g2s(buf[c % 3], src + (size_t)(c + 3) * 12288, 12288, &mbar[c % 3]);
        }
    }
#pragma unroll
    for (int j = 0; j < 6; j++) atomicAdd(&out[j * 256 + t], acc[j]);
}

extern "C" void kernel_launch(void* const* d_in, const int* in_sizes, int n_in,
                              void* d_out, int out_size) {
    const float* x  = (const float*)d_in[0];
    const float* kp = (const float*)d_in[1];
    const float* vp = (const float*)d_in[2];
    const float* Wq = (const float*)d_in[3];
    const float* bq = (const float*)d_in[4];
    const float* Wk = (const float*)d_in[5];
    const float* bk = (const float*)d_in[6];
    const float* Wv = (const float*)d_in[7];
    const float* bv = (const float*)d_in[8];
    const float* Wo = (const float*)d_in[9];
    const float* bo = (const float*)d_in[10];
    const float* Wg = (const float*)d_in[11];
    const float* bg = (const float*)d_in[12];
    const float* Wu = (const float*)d_in[13];
    const float* bu = (const float*)d_in[14];
    const float* Wd = (const float*)d_in[15];
    const float* bd = (const float*)d_in[16];

    k_qkv <<<344, 512>>>(x, Wq, bq, Wk, bk, Wv, bv, bg, bu);
    k_attn<<<256, 256>>>(kp, vp);
    k_comb<<<16,  256>>>(x, bo);
    k_wo  <<<256, 256>>>(Wo);
    k_gu  <<<384, 256>>>(Wg, Wu);
    k_mid <<<15,  512>>>(bd, (float*)d_out);
    k_down<<<384, 256>>>(Wd, (float*)d_out);
}

// round 15
// speedup vs baseline: 1.5040x; 1.1561x over previous
#include <cuda_runtime.h>
#include <cstdint>

#define NQ 8
#define HD 256
#define S_TOT 8192
#define PAST 8191
#define HID 1536
#define INTER 6144
#define QDIM 2048
#define SCALE 0.0625f
#define NCHUNK 256          // 8192 / 32
#define CHUNK 32

// -------- scratch (device globals) --------
__device__ float g_qkv[2560];              // q[0:2048] (pre-scaled), k_new[2048:2304], v_new[2304:2560]
__device__ float g_avpart[NCHUNK * 2048];  // per-chunk partial AV
__device__ float g_stm[NCHUNK * 8];
__device__ float g_stl[NCHUNK * 8];
__device__ float g_attn[QDIM];
__device__ float g_h1[HID];                // preset x+bo by k_comb; k_wo atomics add
__device__ float g_gate[INTER];            // preset bg by k_qkv tail blocks; k_gu atomics add
__device__ float g_up[INTER];              // preset bu by k_qkv tail blocks; k_gu atomics add

static __device__ __forceinline__ float4 f4add(float4 a, float4 b) {
    a.x += b.x; a.y += b.y; a.z += b.z; a.w += b.w; return a;
}
static __device__ __forceinline__ void f4fma(float4& a, float s, float4 w) {
    a.x += s * w.x; a.y += s * w.y; a.z += s * w.z; a.w += s * w.w;
}
static __device__ __forceinline__ float gelu_exact(float v) {
    return 0.5f * v * (1.0f + erff(v * 0.70710678118654752f));
}
template<int PMIN>
static __device__ __forceinline__ float4 wred(float4 v) {
#pragma unroll
    for (int off = 16; off >= PMIN; off >>= 1) {
        v.x += __shfl_xor_sync(0xffffffffu, v.x, off);
        v.y += __shfl_xor_sync(0xffffffffu, v.y, off);
        v.z += __shfl_xor_sync(0xffffffffu, v.z, off);
        v.w += __shfl_xor_sync(0xffffffffu, v.w, off);
    }
    return v;
}
static __device__ __forceinline__ uint32_t smem_u32(const void* p) {
    return (uint32_t)__cvta_generic_to_shared(p);
}
// ---- bulk-DMA (TMA-engine) helpers ----
static __device__ __forceinline__ void mb_init(void* m) {
    asm volatile("mbarrier.init.shared.b64 [%0], 1;" :: "r"(smem_u32(m)));
}
static __device__ __forceinline__ void mb_expect(void* m, int bytes) {
    asm volatile("mbarrier.arrive.expect_tx.shared.b64 _, [%0], %1;"
                 :: "r"(smem_u32(m)), "r"(bytes));
}
static __device__ __forceinline__ void bulk_g2s(void* dst, const void* src, int bytes, void* m) {
    asm volatile("cp.async.bulk.shared::cluster.global.mbarrier::complete_tx::bytes "
                 "[%0], [%1], %2, [%3];"
                 :: "r"(smem_u32(dst)), "l"(src), "r"(bytes), "r"(smem_u32(m)) : "memory");
}
static __device__ __forceinline__ void mb_wait(void* m, int parity) {
    asm volatile("{\n\t.reg .pred P;\nWL_%=:\n\t"
                 "mbarrier.try_wait.parity.shared.b64 P, [%0], %1;\n\t"
                 "@!P bra WL_%=;\n\t}"
                 :: "r"(smem_u32(m)), "r"(parity) : "memory");
}

// ============ K1: QKV projection (+bias, q pre-scaled); tail blocks preset g_gate/g_up ====
// 344 blocks x 512 thr. Blocks 0..319 = QKV; blocks 320..343 preset gate/up biases.
__global__ __launch_bounds__(512) void k_qkv(
        const float* __restrict__ x,
        const float* __restrict__ Wq, const float* __restrict__ bq,
        const float* __restrict__ Wk, const float* __restrict__ bk,
        const float* __restrict__ Wv, const float* __restrict__ bv,
        const float* __restrict__ bg, const float* __restrict__ bu) {
    __shared__ float4 part[16 * 2];
    int t = threadIdx.x, lane = t & 31, wid = t >> 5;
    if (blockIdx.x >= 320) {
        int b = blockIdx.x - 320;          // 0..23
        if (b < 12) g_gate[b * 512 + t] = bg[b * 512 + t];
        else        g_up[(b - 12) * 512 + t] = bu[(b - 12) * 512 + t];
        return;
    }
    int c4 = t & 1, rg = t >> 1;
    int colBase = blockIdx.x * 8;
    const float* W; const float* bias; int ld, wcol; float sc;
    if (blockIdx.x < 256)      { W = Wq; bias = bq; ld = 2048; wcol = colBase;        sc = SCALE; }
    else if (blockIdx.x < 288) { W = Wk; bias = bk; ld = 256;  wcol = colBase - 2048; sc = 1.0f; }
    else                       { W = Wv; bias = bv; ld = 256;  wcol = colBase - 2304; sc = 1.0f; }
    const float* wp = W + wcol + c4 * 4;
    float4 acc = make_float4(0.f, 0.f, 0.f, 0.f);
    int r0 = rg * 6;
#pragma unroll
    for (int i = 0; i < 6; i++) {
        int r = r0 + i;
        float xv = __ldg(x + r);
        float4 w = *(const float4*)(wp + (size_t)r * ld);
        f4fma(acc, xv, w);
    }
    cudaTriggerProgrammaticLaunchCompletion();
    acc = wred<2>(acc);
    if (lane < 2) part[wid * 2 + lane] = acc;
    __syncthreads();
    if (t < 2) {
        float4 s = part[t];
#pragma unroll
        for (int w = 1; w < 16; w++) s = f4add(s, part[w * 2 + t]);
        int col = wcol + t * 4;
        float4 b = *(const float4*)(bias + col);
        s = f4add(s, b);
        s.x *= sc; s.y *= sc; s.z *= sc; s.w *= sc;
        *(float4*)&g_qkv[colBase + t * 4] = s;
    }
}

// ============ K2: fused flash-decode partial ============ (R6 core + PDL)
__global__ __launch_bounds__(256, 2) void k_attn(
        const float* __restrict__ kp, const float* __restrict__ vp) {
    __shared__ float s_sm[8][CHUNK];
    __shared__ float4 red[4 * 8 * 64];
    int t = threadIdx.x, lane = t & 31, wid = t >> 5;
    int c = blockIdx.x;
    int sBase = c * CHUNK;
    cudaGridDependencySynchronize();       // wait for g_qkv
    cudaTriggerProgrammaticLaunchCompletion();
    float4 qa[8], qb[8];
#pragma unroll
    for (int h = 0; h < 8; h++) {
        qa[h] = *(const float4*)(g_qkv + h * 256 + lane * 8);
        qb[h] = *(const float4*)(g_qkv + h * 256 + lane * 8 + 4);
    }
#pragma unroll
    for (int it = 0; it < 2; it++) {
        int r0 = sBase + wid * 4 + it * 2;
        int r1 = r0 + 1;
        const float* kr0 = (r0 < PAST) ? (kp + (size_t)r0 * 256) : (g_qkv + 2048);
        const float* kr1 = (r1 < PAST) ? (kp + (size_t)r1 * 256) : (g_qkv + 2048);
        float4 ka0 = *(const float4*)(kr0 + lane * 8);
        float4 kb0 = *(const float4*)(kr0 + lane * 8 + 4);
        float4 ka1 = *(const float4*)(kr1 + lane * 8);
        float4 kb1 = *(const float4*)(kr1 + lane * 8 + 4);
        float a0[8], a1[8];
#pragma unroll
        for (int h = 0; h < 8; h++) {
            a0[h] = qa[h].x * ka0.x + qa[h].y * ka0.y + qa[h].z * ka0.z + qa[h].w * ka0.w
                  + qb[h].x * kb0.x + qb[h].y * kb0.y + qb[h].z * kb0.z + qb[h].w * kb0.w;
            a1[h] = qa[h].x * ka1.x + qa[h].y * ka1.y + qa[h].z * ka1.z + qa[h].w * ka1.w
                  + qb[h].x * kb1.x + qb[h].y * kb1.y + qb[h].z * kb1.z + qb[h].w * kb1.w;
        }
#pragma unroll
        for (int h = 0; h < 8; h++) {
#pragma unroll
            for (int off = 16; off; off >>= 1) {
                a0[h] += __shfl_xor_sync(0xffffffffu, a0[h], off);
                a1[h] += __shfl_xor_sync(0xffffffffu, a1[h], off);
            }
        }
        if (lane < 8) {
            s_sm[lane][wid * 4 + it * 2]     = a0[lane];
            s_sm[lane][wid * 4 + it * 2 + 1] = a1[lane];
        }
    }
    __syncthreads();
    {
        float s = s_sm[wid][lane];
        float m = s;
#pragma unroll
        for (int off = 16; off; off >>= 1) m = fmaxf(m, __shfl_xor_sync(0xffffffffu, m, off));
        float p = __expf(s - m);
        float l = p;
#pragma unroll
        for (int off = 16; off; off >>= 1) l += __shfl_xor_sync(0xffffffffu, l, off);
        s_sm[wid][lane] = p;
        if (lane == 0) { g_stm[c * 8 + wid] = m; g_stl[c * 8 + wid] = l; }
    }
    __syncthreads();
    int d4 = t & 63, g = t >> 6;
    float4 acc[8];
#pragma unroll
    for (int h = 0; h < 8; h++) acc[h] = make_float4(0.f, 0.f, 0.f, 0.f);
    float4 v[8];
#pragma unroll
    for (int j = 0; j < 8; j++) {
        int s = sBase + g * 8 + j;
        const float* vrow = (s < PAST) ? (vp + (size_t)s * 256) : (g_qkv + 2304);
        v[j] = *(const float4*)(vrow + d4 * 4);
    }
#pragma unroll
    for (int j = 0; j < 8; j++) {
        int pos = g * 8 + j;
#pragma unroll
        for (int h = 0; h < 8; h++) f4fma(acc[h], s_sm[h][pos], v[j]);
    }
#pragma unroll
    for (int h = 0; h < 8; h++) red[g * 512 + h * 64 + d4] = acc[h];
    __syncthreads();
    float4* outp = (float4*)(g_avpart + (size_t)c * 2048);
#pragma unroll
    for (int k = 0; k < 2; k++) {
        int o = t + k * 256;
        float4 s = f4add(f4add(red[o], red[512 + o]), f4add(red[1024 + o], red[1536 + o]));
        outp[o] = s;
    }
}

// ============ K3: combine -> g_attn; preset g_h1 = x + bo ============ (+PDL)
__global__ __launch_bounds__(256) void k_comb(
        const float* __restrict__ x, const float* __restrict__ bo) {
    __shared__ float w_sm[NCHUNK * 8];
    __shared__ float4 red2[256];
    int t = threadIdx.x, lane = t & 31, wid = t >> 5;
    cudaGridDependencySynchronize();
    cudaTriggerProgrammaticLaunchCompletion();
    float mv[8], lv[8];
#pragma unroll
    for (int i = 0; i < 8; i++) {
        int c = lane * 8 + i;
        mv[i] = g_stm[c * 8 + wid];
        lv[i] = g_stl[c * 8 + wid];
    }
    float M = mv[0];
#pragma unroll
    for (int i = 1; i < 8; i++) M = fmaxf(M, mv[i]);
#pragma unroll
    for (int off = 16; off; off >>= 1) M = fmaxf(M, __shfl_xor_sync(0xffffffffu, M, off));
    float L = 0.f;
#pragma unroll
    for (int i = 0; i < 8; i++) L += __expf(mv[i] - M) * lv[i];
#pragma unroll
    for (int off = 16; off; off >>= 1) L += __shfl_xor_sync(0xffffffffu, L, off);
    float invL = 1.0f / L;
#pragma unroll
    for (int i = 0; i < 8; i++) {
        int c = lane * 8 + i;
        w_sm[c * 8 + wid] = __expf(mv[i] - M) * invL;
    }
    if (blockIdx.x < 6) {
        int idx = blockIdx.x * 256 + t;
        g_h1[idx] = x[idx] + bo[idx];
    }
    __syncthreads();
    int oLoc = t >> 3, sl = t & 7;
    int o = blockIdx.x * 32 + oLoc;
    int h = o >> 6;
    float4 acc = make_float4(0.f, 0.f, 0.f, 0.f);
#pragma unroll
    for (int b = 0; b < 4; b++) {
        float4 vv[8];
#pragma unroll
        for (int i = 0; i < 8; i++) {
            int c = sl * 32 + b * 8 + i;
            vv[i] = *(const float4*)(g_avpart + (size_t)c * 2048 + o * 4);
        }
#pragma unroll
        for (int i = 0; i < 8; i++) {
            int c = sl * 32 + b * 8 + i;
            f4fma(acc, w_sm[c * 8 + h], vv[i]);
        }
    }
    red2[t] = acc;
    __syncthreads();
    if (t < 32) {
        float4 s = red2[t * 8];
#pragma unroll
        for (int i = 1; i < 8; i++) s = f4add(s, red2[t * 8 + i]);
        ((float4*)g_attn)[blockIdx.x * 32 + t] = s;
    }
}

// ============ K4: g_h1 += attn @ Wo  (bulk-DMA ring-3; DMA issued BEFORE grid sync) ====
// 256 blocks x 256. 4 chunks x 12KB (2 rows each).
__global__ __launch_bounds__(256) void k_wo(const float* __restrict__ Wo) {
    __shared__ __align__(128) float buf[3][3072];
    __shared__ __align__(8) unsigned long long mbar[3];
    int t = threadIdx.x;
    int r0 = blockIdx.x * 8;
    const char* src = (const char*)(Wo + (size_t)r0 * 1536);
    if (t < 3) mb_init(&mbar[t]);
    __syncthreads();
    if (t == 0) {
#pragma unroll
        for (int b = 0; b < 3; b++) {
            mb_expect(&mbar[b], 12288);
            bulk_g2s(buf[b], src + b * 12288, 12288, &mbar[b]);
        }
    }
    cudaGridDependencySynchronize();       // weights stream during k_comb tail
    cudaTriggerProgrammaticLaunchCompletion();
    float acc[6];
#pragma unroll
    for (int j = 0; j < 6; j++) acc[j] = 0.f;
#pragma unroll
    for (int c = 0; c < 4; c++) {
        mb_wait(&mbar[c % 3], (c / 3) & 1);
        const float* cb = buf[c % 3];
        float x0 = g_attn[r0 + c * 2], x1 = g_attn[r0 + c * 2 + 1];
#pragma unroll
        for (int j = 0; j < 6; j++)
            acc[j] += x0 * cb[j * 256 + t] + x1 * cb[1536 + j * 256 + t];
        __syncthreads();
        if (c + 3 < 4 && t == 0) {
            mb_expect(&mbar[c % 3], 12288);
            bulk_g2s(buf[c % 3], src + (c + 3) * 12288, 12288, &mbar[c % 3]);
        }
    }
#pragma unroll
    for (int j = 0; j < 6; j++) atomicAdd(&g_h1[j * 256 + t], acc[j]);
}

// ============ K5: gate/up accumulation (bulk-DMA ring-3; DMA before sync) ============
// 387 blocks x 256. b<192: Wg stripe; b<384: Wu stripe; b>=384: preset out = h1+bd.
__global__ __launch_bounds__(256) void k_gu(
        const float* __restrict__ Wg, const float* __restrict__ Wu,
        const float* __restrict__ bd, float* __restrict__ out) {
    __shared__ __align__(128) float buf[3][3072];
    __shared__ __align__(8) unsigned long long mbar[3];
    int t = threadIdx.x, b = blockIdx.x;
    if (b >= 384) {
        cudaGridDependencySynchronize();
        cudaTriggerProgrammaticLaunchCompletion();
        int i0 = (b - 384) * 512 + t;
        out[i0] = g_h1[i0] + bd[i0];
        out[i0 + 256] = g_h1[i0 + 256] + bd[i0 + 256];
        return;
    }
    int mat = (b >= 192);
    int stripe = mat ? (b - 192) : b;
    int r0 = stripe * 8;
    const char* src = (const char*)((mat ? Wu : Wg) + (size_t)r0 * 6144);
    if (t < 3) mb_init(&mbar[t]);
    __syncthreads();
    if (t == 0) {
#pragma unroll
        for (int bb = 0; bb < 3; bb++) {
            mb_expect(&mbar[bb], 12288);
            bulk_g2s(buf[bb], src + bb * 12288, 12288, &mbar[bb]);
        }
    }
    cudaGridDependencySynchronize();       // weights stream during k_wo
    cudaTriggerProgrammaticLaunchCompletion();
    float acc[24];
#pragma unroll
    for (int j = 0; j < 24; j++) acc[j] = 0.f;
#pragma unroll
    for (int c = 0; c < 16; c++) {
        mb_wait(&mbar[c % 3], (c / 3) & 1);
        const float* cb = buf[c % 3];
        float xv = g_h1[r0 + (c >> 1)];
        int aBase = (c & 1) * 12;
#pragma unroll
        for (int j = 0; j < 12; j++) acc[aBase + j] += xv * cb[j * 256 + t];
        __syncthreads();
        if (c + 3 < 16 && t == 0) {
            mb_expect(&mbar[c % 3], 12288);
            bulk_g2s(buf[c % 3], src + (size_t)(c + 3) * 12288, 12288, &mbar[c % 3]);
        }
    }
    float* dst = mat ? g_up : g_gate;
#pragma unroll
    for (int j = 0; j < 24; j++) atomicAdd(&dst[j * 256 + t], acc[j]);
}

// ============ K6: out += mid @ Wd  (mid computed in-block from gate/up; DMA before sync) ==
// 384 blocks x 256. 8 chunks x 12KB (2 rows each).
__global__ __launch_bounds__(256) void k_down(
        const float* __restrict__ Wd, float* __restrict__ out) {
    __shared__ __align__(128) float buf[3][3072];
    __shared__ __align__(8) unsigned long long mbar[3];
    __shared__ float mids[16];
    int t = threadIdx.x;
    int r0 = blockIdx.x * 16;
    const char* src = (const char*)(Wd + (size_t)r0 * 1536);
    if (t < 3) mb_init(&mbar[t]);
    __syncthreads();
    if (t == 0) {
#pragma unroll
        for (int b = 0; b < 3; b++) {
            mb_expect(&mbar[b], 12288);
            bulk_g2s(buf[b], src + b * 12288, 12288, &mbar[b]);
        }
    }
    cudaGridDependencySynchronize();       // weights stream during k_gu
    cudaTriggerProgrammaticLaunchCompletion();
    if (t < 16) mids[t] = gelu_exact(g_gate[r0 + t]) * g_up[r0 + t];
    __syncthreads();
    float acc[6];
#pragma unroll
    for (int j = 0; j < 6; j++) acc[j] = 0.f;
#pragma unroll
    for (int c = 0; c < 8; c++) {
        mb_wait(&mbar[c % 3], (c / 3) & 1);
        const float* cb = buf[c % 3];
        float x0 = mids[c * 2], x1 = mids[c * 2 + 1];
#pragma unroll
        for (int j = 0; j < 6; j++)
            acc[j] += x0 * cb[j * 256 + t] + x1 * cb[1536 + j * 256 + t];
        __syncthreads();
        if (c + 3 < 8 && t == 0) {
            mb_expect(&mbar[c % 3], 12288);
            bulk_g2s(buf[c % 3], src + (size_t)(c + 3) * 12288, 12288, &mbar[c % 3]);
        }
    }
#pragma unroll
    for (int j = 0; j < 6; j++) atomicAdd(&out[j * 256 + t], acc[j]);
}

// ---- host: PDL launch helper ----
template <typename Fn, typename... Args>
static void launch_pdl(Fn fn, int grid, int block, Args... args) {
    cudaLaunchConfig_t cfg = {};
    cfg.gridDim = dim3(grid, 1, 1);
    cfg.blockDim = dim3(block, 1, 1);
    cfg.dynamicSmemBytes = 0;
    cfg.stream = 0;
    cudaLaunchAttribute at[1];
    at[0].id = cudaLaunchAttributeProgrammaticStreamSerialization;
    at[0].val.programmaticStreamSerializationAllowed = 1;
    cfg.attrs = at;
    cfg.numAttrs = 1;
    cudaLaunchKernelEx(&cfg, fn, args...);
}

extern "C" void kernel_launch(void* const* d_in, const int* in_sizes, int n_in,
                              void* d_out, int out_size) {
    const float* x  = (const float*)d_in[0];
    const float* kp = (const float*)d_in[1];
    const float* vp = (const float*)d_in[2];
    const float* Wq = (const float*)d_in[3];
    const float* bq = (const float*)d_in[4];
    const float* Wk = (const float*)d_in[5];
    const float* bk = (const float*)d_in[6];
    const float* Wv = (const float*)d_in[7];
    const float* bv = (const float*)d_in[8];
    const float* Wo = (const float*)d_in[9];
    const float* bo = (const float*)d_in[10];
    const float* Wg = (const float*)d_in[11];
    const float* bg = (const float*)d_in[12];
    const float* Wu = (const float*)d_in[13];
    const float* bu = (const float*)d_in[14];
    const float* Wd = (const float*)d_in[15];
    const float* bd = (const float*)d_in[16];
    float* out = (float*)d_out;

    k_qkv<<<344, 512>>>(x, Wq, bq, Wk, bk, Wv, bv, bg, bu);
    launch_pdl(k_attn, 256, 256, kp, vp);
    launch_pdl(k_comb, 16, 256, x, bo);
    launch_pdl(k_wo, 256, 256, Wo);
    launch_pdl(k_gu, 387, 256, Wg, Wu, bd, out);
    launch_pdl(k_down, 384, 256, Wd, out);
}

// round 16
// speedup vs baseline: 1.5077x; 1.0025x over previous
#include <cuda_runtime.h>
#include <cstdint>

#define NQ 8
#define HD 256
#define S_TOT 8192
#define PAST 8191
#define HID 1536
#define INTER 6144
#define QDIM 2048
#define SCALE 0.0625f
#define NCHUNK 256          // 8192 / 32
#define CHUNK 32

// -------- scratch (device globals) --------
__device__ float g_qkv[2560];              // q[0:2048] (pre-scaled), k_new[2048:2304], v_new[2304:2560]
__device__ float g_avpart[NCHUNK * 2048];  // per-chunk partial AV
__device__ float g_stm[NCHUNK * 8];
__device__ float g_stl[NCHUNK * 8];
__device__ float g_attn[QDIM];
__device__ float g_h1[HID];                // preset x+bo by k_comb; k_wo atomics add
__device__ float g_gate[INTER];            // preset bg by k_qkv tail blocks; k_gu atomics add
__device__ float g_up[INTER];              // preset bu by k_qkv tail blocks; k_gu atomics add

static __device__ __forceinline__ float4 f4add(float4 a, float4 b) {
    a.x += b.x; a.y += b.y; a.z += b.z; a.w += b.w; return a;
}
static __device__ __forceinline__ void f4fma(float4& a, float s, float4 w) {
    a.x += s * w.x; a.y += s * w.y; a.z += s * w.z; a.w += s * w.w;
}
static __device__ __forceinline__ float gelu_exact(float v) {
    return 0.5f * v * (1.0f + erff(v * 0.70710678118654752f));
}
template<int PMIN>
static __device__ __forceinline__ float4 wred(float4 v) {
#pragma unroll
    for (int off = 16; off >= PMIN; off >>= 1) {
        v.x += __shfl_xor_sync(0xffffffffu, v.x, off);
        v.y += __shfl_xor_sync(0xffffffffu, v.y, off);
        v.z += __shfl_xor_sync(0xffffffffu, v.z, off);
        v.w += __shfl_xor_sync(0xffffffffu, v.w, off);
    }
    return v;
}
static __device__ __forceinline__ uint32_t smem_u32(const void* p) {
    return (uint32_t)__cvta_generic_to_shared(p);
}
// ---- bulk-DMA (TMA-engine) helpers ----
static __device__ __forceinline__ void mb_init(void* m) {
    asm volatile("mbarrier.init.shared.b64 [%0], 1;" :: "r"(smem_u32(m)));
}
static __device__ __forceinline__ void mb_expect(void* m, int bytes) {
    asm volatile("mbarrier.arrive.expect_tx.shared.b64 _, [%0], %1;"
                 :: "r"(smem_u32(m)), "r"(bytes));
}
static __device__ __forceinline__ void bulk_g2s(void* dst, const void* src, int bytes, void* m) {
    asm volatile("cp.async.bulk.shared::cluster.global.mbarrier::complete_tx::bytes "
                 "[%0], [%1], %2, [%3];"
                 :: "r"(smem_u32(dst)), "l"(src), "r"(bytes), "r"(smem_u32(m)) : "memory");
}
static __device__ __forceinline__ void mb_wait(void* m, int parity) {
    asm volatile("{\n\t.reg .pred P;\nWL_%=:\n\t"
                 "mbarrier.try_wait.parity.shared.b64 P, [%0], %1;\n\t"
                 "@!P bra WL_%=;\n\t}"
                 :: "r"(smem_u32(m)), "r"(parity) : "memory");
}

// ============ K1: QKV projection (+bias, q pre-scaled); tail blocks preset g_gate/g_up ====
// 344 blocks x 512 thr. Blocks 0..319 = QKV; blocks 320..343 preset gate/up biases.
__global__ __launch_bounds__(512) void k_qkv(
        const float* __restrict__ x,
        const float* __restrict__ Wq, const float* __restrict__ bq,
        const float* __restrict__ Wk, const float* __restrict__ bk,
        const float* __restrict__ Wv, const float* __restrict__ bv,
        const float* __restrict__ bg, const float* __restrict__ bu) {
    __shared__ float4 part[16 * 2];
    int t = threadIdx.x, lane = t & 31, wid = t >> 5;
    if (blockIdx.x >= 320) {
        int b = blockIdx.x - 320;          // 0..23
        if (b < 12) g_gate[b * 512 + t] = bg[b * 512 + t];
        else        g_up[(b - 12) * 512 + t] = bu[(b - 12) * 512 + t];
        return;
    }
    int c4 = t & 1, rg = t >> 1;
    int colBase = blockIdx.x * 8;
    const float* W; const float* bias; int ld, wcol; float sc;
    if (blockIdx.x < 256)      { W = Wq; bias = bq; ld = 2048; wcol = colBase;        sc = SCALE; }
    else if (blockIdx.x < 288) { W = Wk; bias = bk; ld = 256;  wcol = colBase - 2048; sc = 1.0f; }
    else                       { W = Wv; bias = bv; ld = 256;  wcol = colBase - 2304; sc = 1.0f; }
    const float* wp = W + wcol + c4 * 4;
    float4 acc = make_float4(0.f, 0.f, 0.f, 0.f);
    int r0 = rg * 6;
#pragma unroll
    for (int i = 0; i < 6; i++) {
        int r = r0 + i;
        float xv = __ldg(x + r);
        float4 w = *(const float4*)(wp + (size_t)r * ld);
        f4fma(acc, xv, w);
    }
    cudaTriggerProgrammaticLaunchCompletion();
    acc = wred<2>(acc);
    if (lane < 2) part[wid * 2 + lane] = acc;
    __syncthreads();
    if (t < 2) {
        float4 s = part[t];
#pragma unroll
        for (int w = 1; w < 16; w++) s = f4add(s, part[w * 2 + t]);
        int col = wcol + t * 4;
        float4 b = *(const float4*)(bias + col);
        s = f4add(s, b);
        s.x *= sc; s.y *= sc; s.z *= sc; s.w *= sc;
        *(float4*)&g_qkv[colBase + t * 4] = s;
    }
}

// ============ K2: flash-decode partial; K+V PRELOADED before grid sync ============
// 256 blocks x 256 thr.
__global__ __launch_bounds__(256) void k_attn(
        const float* __restrict__ kp, const float* __restrict__ vp) {
    __shared__ float s_sm[8][CHUNK];
    __shared__ float4 red[4 * 8 * 64];
    int t = threadIdx.x, lane = t & 31, wid = t >> 5;
    int c = blockIdx.x;
    int sBase = c * CHUNK;
    int d4 = t & 63, g = t >> 6;
    // ---- PRELOAD (no dependency on k_qkv except patched last row) ----
    float4 kA[4], kB[4];               // warp's 4 K rows
#pragma unroll
    for (int i = 0; i < 4; i++) {
        int r = sBase + wid * 4 + i;
        int rc = (r < PAST) ? r : (PAST - 1);
        const float* kr = kp + (size_t)rc * 256;
        kA[i] = *(const float4*)(kr + lane * 8);
        kB[i] = *(const float4*)(kr + lane * 8 + 4);
    }
    float4 vr[8];                      // this thread's 8 V rows (d4 slice)
#pragma unroll
    for (int j = 0; j < 8; j++) {
        int s = sBase + g * 8 + j;
        int sc2 = (s < PAST) ? s : (PAST - 1);
        vr[j] = *(const float4*)(vp + (size_t)sc2 * 256 + d4 * 4);
    }
    cudaTriggerProgrammaticLaunchCompletion();
    cudaGridDependencySynchronize();   // now g_qkv is valid
    // ---- patch appended row (only last chunk) ----
    if (c == NCHUNK - 1) {
#pragma unroll
        for (int i = 0; i < 4; i++) {
            int r = sBase + wid * 4 + i;
            if (r >= PAST) {
                kA[i] = *(const float4*)(g_qkv + 2048 + lane * 8);
                kB[i] = *(const float4*)(g_qkv + 2048 + lane * 8 + 4);
            }
        }
#pragma unroll
        for (int j = 0; j < 8; j++) {
            int s = sBase + g * 8 + j;
            if (s >= PAST) vr[j] = *(const float4*)(g_qkv + 2304 + d4 * 4);
        }
    }
    // ---- Phase 1: scores (q loaded per head; pre-scaled) ----
#pragma unroll
    for (int it = 0; it < 2; it++) {
        float a0[8], a1[8];
#pragma unroll
        for (int h = 0; h < 8; h++) {
            float4 qa = *(const float4*)(g_qkv + h * 256 + lane * 8);
            float4 qb = *(const float4*)(g_qkv + h * 256 + lane * 8 + 4);
            float4 ka0 = kA[it * 2], kb0 = kB[it * 2];
            float4 ka1 = kA[it * 2 + 1], kb1 = kB[it * 2 + 1];
            a0[h] = qa.x * ka0.x + qa.y * ka0.y + qa.z * ka0.z + qa.w * ka0.w
                  + qb.x * kb0.x + qb.y * kb0.y + qb.z * kb0.z + qb.w * kb0.w;
            a1[h] = qa.x * ka1.x + qa.y * ka1.y + qa.z * ka1.z + qa.w * ka1.w
                  + qb.x * kb1.x + qb.y * kb1.y + qb.z * kb1.z + qb.w * kb1.w;
        }
#pragma unroll
        for (int h = 0; h < 8; h++) {
#pragma unroll
            for (int off = 16; off; off >>= 1) {
                a0[h] += __shfl_xor_sync(0xffffffffu, a0[h], off);
                a1[h] += __shfl_xor_sync(0xffffffffu, a1[h], off);
            }
        }
        if (lane < 8) {
            s_sm[lane][wid * 4 + it * 2]     = a0[lane];
            s_sm[lane][wid * 4 + it * 2 + 1] = a1[lane];
        }
    }
    __syncthreads();
    // ---- Phase 2: per-head local softmax ----
    {
        float s = s_sm[wid][lane];
        float m = s;
#pragma unroll
        for (int off = 16; off; off >>= 1) m = fmaxf(m, __shfl_xor_sync(0xffffffffu, m, off));
        float p = __expf(s - m);
        float l = p;
#pragma unroll
        for (int off = 16; off; off >>= 1) l += __shfl_xor_sync(0xffffffffu, l, off);
        s_sm[wid][lane] = p;
        if (lane == 0) { g_stm[c * 8 + wid] = m; g_stl[c * 8 + wid] = l; }
    }
    __syncthreads();
    // ---- Phase 3: p.V using preloaded V ----
    float4 acc[8];
#pragma unroll
    for (int h = 0; h < 8; h++) acc[h] = make_float4(0.f, 0.f, 0.f, 0.f);
#pragma unroll
    for (int j = 0; j < 8; j++) {
        int pos = g * 8 + j;
#pragma unroll
        for (int h = 0; h < 8; h++) f4fma(acc[h], s_sm[h][pos], vr[j]);
    }
#pragma unroll
    for (int h = 0; h < 8; h++) red[g * 512 + h * 64 + d4] = acc[h];
    __syncthreads();
    float4* outp = (float4*)(g_avpart + (size_t)c * 2048);
#pragma unroll
    for (int k = 0; k < 2; k++) {
        int o = t + k * 256;
        float4 s = f4add(f4add(red[o], red[512 + o]), f4add(red[1024 + o], red[1536 + o]));
        outp[o] = s;
    }
}

// ============ K3: combine -> g_attn; preset g_h1 = x + bo ============
__global__ __launch_bounds__(256) void k_comb(
        const float* __restrict__ x, const float* __restrict__ bo) {
    __shared__ float w_sm[NCHUNK * 8];
    __shared__ float4 red2[256];
    int t = threadIdx.x, lane = t & 31, wid = t >> 5;
    cudaTriggerProgrammaticLaunchCompletion();
    cudaGridDependencySynchronize();
    float mv[8], lv[8];
#pragma unroll
    for (int i = 0; i < 8; i++) {
        int c = lane * 8 + i;
        mv[i] = g_stm[c * 8 + wid];
        lv[i] = g_stl[c * 8 + wid];
    }
    float M = mv[0];
#pragma unroll
    for (int i = 1; i < 8; i++) M = fmaxf(M, mv[i]);
#pragma unroll
    for (int off = 16; off; off >>= 1) M = fmaxf(M, __shfl_xor_sync(0xffffffffu, M, off));
    float L = 0.f;
#pragma unroll
    for (int i = 0; i < 8; i++) L += __expf(mv[i] - M) * lv[i];
#pragma unroll
    for (int off = 16; off; off >>= 1) L += __shfl_xor_sync(0xffffffffu, L, off);
    float invL = 1.0f / L;
#pragma unroll
    for (int i = 0; i < 8; i++) {
        int c = lane * 8 + i;
        w_sm[c * 8 + wid] = __expf(mv[i] - M) * invL;
    }
    if (blockIdx.x < 6) {
        int idx = blockIdx.x * 256 + t;
        g_h1[idx] = x[idx] + bo[idx];
    }
    __syncthreads();
    int oLoc = t >> 3, sl = t & 7;
    int o = blockIdx.x * 32 + oLoc;
    int h = o >> 6;
    float4 acc = make_float4(0.f, 0.f, 0.f, 0.f);
#pragma unroll
    for (int b = 0; b < 4; b++) {
        float4 vv[8];
#pragma unroll
        for (int i = 0; i < 8; i++) {
            int c = sl * 32 + b * 8 + i;
            vv[i] = *(const float4*)(g_avpart + (size_t)c * 2048 + o * 4);
        }
#pragma unroll
        for (int i = 0; i < 8; i++) {
            int c = sl * 32 + b * 8 + i;
            f4fma(acc, w_sm[c * 8 + h], vv[i]);
        }
    }
    red2[t] = acc;
    __syncthreads();
    if (t < 32) {
        float4 s = red2[t * 8];
#pragma unroll
        for (int i = 1; i < 8; i++) s = f4add(s, red2[t * 8 + i]);
        ((float4*)g_attn)[blockIdx.x * 32 + t] = s;
    }
}

// ============ K4: g_h1 += attn @ Wo  (ALL 4 chunks up-front; dyn smem 48KB) ============
// 256 blocks x 256.
__global__ __launch_bounds__(256) void k_wo(const float* __restrict__ Wo) {
    extern __shared__ __align__(128) float dbuf[];   // 4 * 3072
    __shared__ __align__(8) unsigned long long mbar[4];
    int t = threadIdx.x;
    int r0 = blockIdx.x * 8;
    const char* src = (const char*)(Wo + (size_t)r0 * 1536);
    if (t < 4) mb_init(&mbar[t]);
    __syncthreads();
    if (t == 0) {
#pragma unroll
        for (int b = 0; b < 4; b++) {
            mb_expect(&mbar[b], 12288);
            bulk_g2s(dbuf + b * 3072, src + b * 12288, 12288, &mbar[b]);
        }
    }
    cudaTriggerProgrammaticLaunchCompletion();
    cudaGridDependencySynchronize();
    float acc[6];
#pragma unroll
    for (int j = 0; j < 6; j++) acc[j] = 0.f;
#pragma unroll
    for (int c = 0; c < 4; c++) {
        mb_wait(&mbar[c], 0);
        const float* cb = dbuf + c * 3072;
        float x0 = g_attn[r0 + c * 2], x1 = g_attn[r0 + c * 2 + 1];
#pragma unroll
        for (int j = 0; j < 6; j++)
            acc[j] += x0 * cb[j * 256 + t] + x1 * cb[1536 + j * 256 + t];
    }
#pragma unroll
    for (int j = 0; j < 6; j++) atomicAdd(&g_h1[j * 256 + t], acc[j]);
}

// ============ K5: gate/up accumulation (ring-8, dyn smem 96KB) ============
// 387 blocks x 256. b<192: Wg stripe; b<384: Wu stripe; b>=384: preset out = h1+bd.
__global__ __launch_bounds__(256) void k_gu(
        const float* __restrict__ Wg, const float* __restrict__ Wu,
        const float* __restrict__ bd, float* __restrict__ out) {
    extern __shared__ __align__(128) float dbuf[];   // 8 * 3072
    __shared__ __align__(8) unsigned long long mbar[8];
    int t = threadIdx.x, b = blockIdx.x;
    if (b >= 384) {
        cudaTriggerProgrammaticLaunchCompletion();
        cudaGridDependencySynchronize();
        int i0 = (b - 384) * 512 + t;
        out[i0] = g_h1[i0] + bd[i0];
        out[i0 + 256] = g_h1[i0 + 256] + bd[i0 + 256];
        return;
    }
    int mat = (b >= 192);
    int stripe = mat ? (b - 192) : b;
    int r0 = stripe * 8;
    const char* src = (const char*)((mat ? Wu : Wg) + (size_t)r0 * 6144);
    if (t < 8) mb_init(&mbar[t]);
    __syncthreads();
    if (t == 0) {
#pragma unroll
        for (int bb = 0; bb < 8; bb++) {
            mb_expect(&mbar[bb], 12288);
            bulk_g2s(dbuf + bb * 3072, src + bb * 12288, 12288, &mbar[bb]);
        }
    }
    cudaTriggerProgrammaticLaunchCompletion();
    cudaGridDependencySynchronize();
    float acc[24];
#pragma unroll
    for (int j = 0; j < 24; j++) acc[j] = 0.f;
#pragma unroll
    for (int c = 0; c < 16; c++) {
        mb_wait(&mbar[c & 7], (c >> 3) & 1);
        const float* cb = dbuf + (c & 7) * 3072;
        float xv = g_h1[r0 + (c >> 1)];
        int aBase = (c & 1) * 12;
#pragma unroll
        for (int j = 0; j < 12; j++) acc[aBase + j] += xv * cb[j * 256 + t];
        if (c + 8 < 16) {
            __syncthreads();
            if (t == 0) {
                mb_expect(&mbar[c & 7], 12288);
                bulk_g2s(dbuf + (c & 7) * 3072, src + (size_t)(c + 8) * 12288, 12288, &mbar[c & 7]);
            }
        }
    }
    float* dst = mat ? g_up : g_gate;
#pragma unroll
    for (int j = 0; j < 24; j++) atomicAdd(&dst[j * 256 + t], acc[j]);
}

// ============ K6: out += mid @ Wd  (ALL 8 chunks up-front; dyn smem 96KB) ============
// 384 blocks x 256.
__global__ __launch_bounds__(256) void k_down(
        const float* __restrict__ Wd, float* __restrict__ out) {
    extern __shared__ __align__(128) float dbuf[];   // 8 * 3072
    __shared__ __align__(8) unsigned long long mbar[8];
    __shared__ float mids[16];
    int t = threadIdx.x;
    int r0 = blockIdx.x * 16;
    const char* src = (const char*)(Wd + (size_t)r0 * 1536);
    if (t < 8) mb_init(&mbar[t]);
    __syncthreads();
    if (t == 0) {
#pragma unroll
        for (int b = 0; b < 8; b++) {
            mb_expect(&mbar[b], 12288);
            bulk_g2s(dbuf + b * 3072, src + b * 12288, 12288, &mbar[b]);
        }
    }
    cudaGridDependencySynchronize();
    if (t < 16) mids[t] = gelu_exact(g_gate[r0 + t]) * g_up[r0 + t];
    __syncthreads();
    float acc[6];
#pragma unroll
    for (int j = 0; j < 6; j++) acc[j] = 0.f;
#pragma unroll
    for (int c = 0; c < 8; c++) {
        mb_wait(&mbar[c], 0);
        const float* cb = dbuf + c * 3072;
        float x0 = mids[c * 2], x1 = mids[c * 2 + 1];
#pragma unroll
        for (int j = 0; j < 6; j++)
            acc[j] += x0 * cb[j * 256 + t] + x1 * cb[1536 + j * 256 + t];
    }
#pragma unroll
    for (int j = 0; j < 6; j++) atomicAdd(&out[j * 256 + t], acc[j]);
}

// ---- host: PDL launch helper ----
template <typename Fn, typename... Args>
static void launch_pdl(Fn fn, int grid, int block, size_t dynSmem, Args... args) {
    cudaLaunchConfig_t cfg = {};
    cfg.gridDim = dim3(grid, 1, 1);
    cfg.blockDim = dim3(block, 1, 1);
    cfg.dynamicSmemBytes = dynSmem;
    cfg.stream = 0;
    cudaLaunchAttribute at[1];
    at[0].id = cudaLaunchAttributeProgrammaticStreamSerialization;
    at[0].val.programmaticStreamSerializationAllowed = 1;
    cfg.attrs = at;
    cfg.numAttrs = 1;
    cudaLaunchKernelEx(&cfg, fn, args...);
}

extern "C" void kernel_launch(void* const* d_in, const int* in_sizes, int n_in,
                              void* d_out, int out_size) {
    const float* x  = (const float*)d_in[0];
    const float* kp = (const float*)d_in[1];
    const float* vp = (const float*)d_in[2];
    const float* Wq = (const float*)d_in[3];
    const float* bq = (const float*)d_in[4];
    const float* Wk = (const float*)d_in[5];
    const float* bk = (const float*)d_in[6];
    const float* Wv = (const float*)d_in[7];
    const float* bv = (const float*)d_in[8];
    const float* Wo = (const float*)d_in[9];
    const float* bo = (const float*)d_in[10];
    const float* Wg = (const float*)d_in[11];
    const float* bg = (const float*)d_in[12];
    const float* Wu = (const float*)d_in[13];
    const float* bu = (const float*)d_in[14];
    const float* Wd = (const float*)d_in[15];
    const float* bd = (const float*)d_in[16];
    float* out = (float*)d_out;

    cudaFuncSetAttribute(k_wo,   cudaFuncAttributeMaxDynamicSharedMemorySize, 49152);
    cudaFuncSetAttribute(k_gu,   cudaFuncAttributeMaxDynamicSharedMemorySize, 98304);
    cudaFuncSetAttribute(k_down, cudaFuncAttributeMaxDynamicSharedMemorySize, 98304);

    k_qkv<<<344, 512>>>(x, Wq, bq, Wk, bk, Wv, bv, bg, bu);
    launch_pdl(k_attn, 256, 256, 0, kp, vp);
    launch_pdl(k_comb, 16, 256, 0, x, bo);
    launch_pdl(k_wo, 256, 256, 49152, Wo);
    launch_pdl(k_gu, 387, 256, 98304, Wg, Wu, bd, out);
    launch_pdl(k_down, 384, 256, 98304, Wd, out);
}